// round 7
// baseline (speedup 1.0000x reference)
#include <cuda_runtime.h>
#include <cuda_bf16.h>
#include <math.h>

#define MAXN 100000
#define MAXE 1600000
#define SCAN_B 1024

// ---------------- scratch (static device globals only) ----------------
__device__ int   g_cnt_in [MAXN];
__device__ int   g_cnt_out[MAXN];
__device__ int   g_fill   [MAXN];
__device__ int   g_rowptr [MAXN + 1];
__device__ int   g_csr_src[MAXE];
__device__ int   g_blocksums[1024];
__device__ float g_dout[MAXN];
__device__ float g_din [MAXN];
__device__ float g_y2  [(size_t)MAXN * 128];
__device__ float g_z   [(size_t)MAXN * 64];

// split-bf16 activation planes (producer-side split; same bytes as fp32)
__device__ __align__(16) __nv_bfloat16 g_agg1h[(size_t)MAXN * 128];
__device__ __align__(16) __nv_bfloat16 g_agg1l[(size_t)MAXN * 128];
__device__ __align__(16) __nv_bfloat16 g_h1h  [(size_t)MAXN * 256];
__device__ __align__(16) __nv_bfloat16 g_h1l  [(size_t)MAXN * 256];
__device__ __align__(16) __nv_bfloat16 g_agg3h[(size_t)MAXN * 64];
__device__ __align__(16) __nv_bfloat16 g_agg3l[(size_t)MAXN * 64];

// split-bf16 transposed weights: W^T stored [n][k], hi + lo planes
__device__ __align__(16) __nv_bfloat16 g_w1t_hi[256 * 128], g_w1t_lo[256 * 128];
__device__ __align__(16) __nv_bfloat16 g_w2t_hi[128 * 256], g_w2t_lo[128 * 256];
__device__ __align__(16) __nv_bfloat16 g_w3t_hi[128 * 64],  g_w3t_lo[128 * 64];

// ---------------- helpers ----------------
__device__ __forceinline__ void mma_bf16(float* c, const unsigned* a, unsigned b0, unsigned b1) {
    asm volatile(
        "mma.sync.aligned.m16n8k16.row.col.f32.bf16.bf16.f32 "
        "{%0,%1,%2,%3}, {%4,%5,%6,%7}, {%8,%9}, {%0,%1,%2,%3};\n"
        : "+f"(c[0]), "+f"(c[1]), "+f"(c[2]), "+f"(c[3])
        : "r"(a[0]), "r"(a[1]), "r"(a[2]), "r"(a[3]), "r"(b0), "r"(b1));
}

__device__ __forceinline__ void split2(float v, __nv_bfloat16& h, __nv_bfloat16& l) {
    h = __float2bfloat16(v);
    l = __float2bfloat16(v - __bfloat162float(h));
}

// split a float4 and store as uint2 pairs into bf16 planes
__device__ __forceinline__ void split_store4(float4 v, __nv_bfloat16* ph, __nv_bfloat16* pl) {
    __nv_bfloat16 h[4], l[4];
    split2(v.x, h[0], l[0]); split2(v.y, h[1], l[1]);
    split2(v.z, h[2], l[2]); split2(v.w, h[3], l[3]);
    *reinterpret_cast<uint2*>(ph) = *reinterpret_cast<uint2*>(h);
    *reinterpret_cast<uint2*>(pl) = *reinterpret_cast<uint2*>(l);
}

// ---------------- weight preprocessing + counter zero (merged) ----------------
__global__ void prep_kernel(const float* __restrict__ W1, const float* __restrict__ W2,
                            const float* __restrict__ W3, int N) {
    int i = blockIdx.x * blockDim.x + threadIdx.x;
    if (i < N) { g_cnt_in[i] = 0; g_cnt_out[i] = 0; g_fill[i] = 0; }
    if (i < 128 * 256) {                 // W1 [k=128][n=256] -> T[n][k]
        int k = i >> 8, n = i & 255;
        split2(W1[i], g_w1t_hi[n * 128 + k], g_w1t_lo[n * 128 + k]);
    }
    if (i < 256 * 128) {                 // W2 [k=256][n=128] -> T[n][k]
        int k = i >> 7, n = i & 127;
        split2(W2[i], g_w2t_hi[n * 256 + k], g_w2t_lo[n * 256 + k]);
    }
    if (i < 64 * 128) {                  // W3 [k=64][n=128] -> T[n][k]
        int k = i >> 7, n = i & 127;
        split2(W3[i], g_w3t_hi[n * 64 + k], g_w3t_lo[n * 64 + k]);
    }
}

// ---------------- CSR build ----------------
__global__ void hist_kernel(const int* __restrict__ src, const int* __restrict__ dst, int E) {
    int i = (blockIdx.x * blockDim.x + threadIdx.x) * 4;
    if (i + 3 < E) {
        int4 s = *reinterpret_cast<const int4*>(src + i);
        int4 d = *reinterpret_cast<const int4*>(dst + i);
        atomicAdd(&g_cnt_out[s.x], 1); atomicAdd(&g_cnt_out[s.y], 1);
        atomicAdd(&g_cnt_out[s.z], 1); atomicAdd(&g_cnt_out[s.w], 1);
        atomicAdd(&g_cnt_in [d.x], 1); atomicAdd(&g_cnt_in [d.y], 1);
        atomicAdd(&g_cnt_in [d.z], 1); atomicAdd(&g_cnt_in [d.w], 1);
    } else {
        for (; i < E; ++i) {
            atomicAdd(&g_cnt_out[src[i]], 1);
            atomicAdd(&g_cnt_in [dst[i]], 1);
        }
    }
}

__global__ void scan_part(int N) {
    __shared__ int sm[SCAN_B];
    int tid = threadIdx.x;
    int i = blockIdx.x * SCAN_B + tid;
    int v = (i < N) ? g_cnt_in[i] : 0;
    sm[tid] = v;
    __syncthreads();
    #pragma unroll
    for (int off = 1; off < SCAN_B; off <<= 1) {
        int t = (tid >= off) ? sm[tid - off] : 0;
        __syncthreads();
        sm[tid] += t;
        __syncthreads();
    }
    if (i < N) g_rowptr[i] = sm[tid] - v;
    if (tid == SCAN_B - 1) g_blocksums[blockIdx.x] = sm[tid];
}

__global__ void scan_tops(int nb) {
    if (threadIdx.x == 0) {
        int acc = 0;
        for (int b = 0; b < nb; ++b) { int t = g_blocksums[b]; g_blocksums[b] = acc; acc += t; }
    }
}

// scan finalize + rsqrt degrees (merged)
__global__ void scan_add(int N, int E) {
    int i = blockIdx.x * blockDim.x + threadIdx.x;
    if (i < N) {
        g_rowptr[i] += g_blocksums[i / SCAN_B];
        g_dout[i] = rsqrtf((float)max(g_cnt_out[i], 1));
        g_din [i] = rsqrtf((float)max(g_cnt_in [i], 1));
    }
    if (i == 0) g_rowptr[N] = E;
}

__global__ void fill_kernel(const int* __restrict__ src, const int* __restrict__ dst, int E) {
    int i = (blockIdx.x * blockDim.x + threadIdx.x) * 4;
    if (i + 3 < E) {
        int4 s = *reinterpret_cast<const int4*>(src + i);
        int4 d = *reinterpret_cast<const int4*>(dst + i);
        int p;
        p = g_rowptr[d.x] + atomicAdd(&g_fill[d.x], 1); g_csr_src[p] = s.x;
        p = g_rowptr[d.y] + atomicAdd(&g_fill[d.y], 1); g_csr_src[p] = s.y;
        p = g_rowptr[d.z] + atomicAdd(&g_fill[d.z], 1); g_csr_src[p] = s.z;
        p = g_rowptr[d.w] + atomicAdd(&g_fill[d.w], 1); g_csr_src[p] = s.w;
    } else {
        for (; i < E; ++i) {
            int d = dst[i];
            int pos = g_rowptr[d] + atomicAdd(&g_fill[d], 1);
            g_csr_src[pos] = src[i];
        }
    }
}

// ---------------- gathers (atomic-free CSR, shfl-batched indices) ----------------
// layer1: agg1 = din * segsum(dout * x), D=128, warp/node, split-bf16 output
__global__ void gather_d128_l1(const float* __restrict__ x, int N) {
    int t = blockIdx.x * blockDim.x + threadIdx.x;
    int node = t >> 5, lane = t & 31;
    if (node >= N) return;
    int beg = g_rowptr[node], end = g_rowptr[node + 1];
    const float4* x4 = reinterpret_cast<const float4*>(x);
    float4 acc = make_float4(0.f, 0.f, 0.f, 0.f);
    for (int base = beg; base < end; base += 32) {
        int cnt = min(32, end - base);
        int idx = 0; float w = 0.f;
        if (lane < cnt) { idx = __ldg(g_csr_src + base + lane); w = __ldg(g_dout + idx); }
        #pragma unroll 4
        for (int j = 0; j < cnt; ++j) {
            int s   = __shfl_sync(0xffffffffu, idx, j);
            float ww = __shfl_sync(0xffffffffu, w, j);
            float4 v = __ldg(x4 + (size_t)s * 32 + lane);
            acc.x = fmaf(ww, v.x, acc.x);
            acc.y = fmaf(ww, v.y, acc.y);
            acc.z = fmaf(ww, v.z, acc.z);
            acc.w = fmaf(ww, v.w, acc.w);
        }
    }
    float di = g_din[node];
    acc.x *= di; acc.y *= di; acc.z *= di; acc.w *= di;
    size_t o = (size_t)node * 128 + lane * 4;
    split_store4(acc, g_agg1h + o, g_agg1l + o);
}

// layer2 fused VAE epilogue: ml = din * segsum(y2) + b2; split; z = eps*exp(.5lv)+mean
__global__ void gather_d128_l2_vae(const float* __restrict__ b2, const float* __restrict__ eps,
                                   float* __restrict__ out_mean, float* __restrict__ out_lv, int N) {
    int t = blockIdx.x * blockDim.x + threadIdx.x;
    int node = t >> 5, lane = t & 31;
    if (node >= N) return;
    int beg = g_rowptr[node], end = g_rowptr[node + 1];
    const float4* y4 = reinterpret_cast<const float4*>(g_y2);
    float4 acc = make_float4(0.f, 0.f, 0.f, 0.f);
    for (int base = beg; base < end; base += 32) {
        int cnt = min(32, end - base);
        int idx = 0;
        if (lane < cnt) idx = __ldg(g_csr_src + base + lane);
        #pragma unroll 4
        for (int j = 0; j < cnt; ++j) {
            int s = __shfl_sync(0xffffffffu, idx, j);
            float4 v = __ldg(y4 + (size_t)s * 32 + lane);
            acc.x += v.x; acc.y += v.y; acc.z += v.z; acc.w += v.w;
        }
    }
    float di = g_din[node];
    float4 bb = __ldg(reinterpret_cast<const float4*>(b2) + lane);
    acc.x = fmaf(acc.x, di, bb.x);
    acc.y = fmaf(acc.y, di, bb.y);
    acc.z = fmaf(acc.z, di, bb.z);
    acc.w = fmaf(acc.w, di, bb.w);
    float4 other;
    other.x = __shfl_xor_sync(0xffffffffu, acc.x, 16);
    other.y = __shfl_xor_sync(0xffffffffu, acc.y, 16);
    other.z = __shfl_xor_sync(0xffffffffu, acc.z, 16);
    other.w = __shfl_xor_sync(0xffffffffu, acc.w, 16);
    if (lane < 16) {
        size_t o = (size_t)node * 16 + lane;
        reinterpret_cast<float4*>(out_mean)[o] = acc;
        float4 e = __ldg(reinterpret_cast<const float4*>(eps) + o);
        float4 z;
        z.x = fmaf(e.x, expf(0.5f * other.x), acc.x);
        z.y = fmaf(e.y, expf(0.5f * other.y), acc.y);
        z.z = fmaf(e.z, expf(0.5f * other.z), acc.z);
        z.w = fmaf(e.w, expf(0.5f * other.w), acc.w);
        reinterpret_cast<float4*>(g_z)[o] = z;
    } else {
        reinterpret_cast<float4*>(out_lv)[(size_t)node * 16 + (lane - 16)] = acc;
    }
}

// layer3: agg3 = din * segsum(dout * z), D=64; full warp, 2 edges per iteration
__global__ void gather_d64_l3(int N) {
    int t = blockIdx.x * blockDim.x + threadIdx.x;
    int node = t >> 5, lane = t & 31;
    if (node >= N) return;
    int beg = g_rowptr[node], end = g_rowptr[node + 1];
    int half = lane >> 4;       // which edge of the pair
    int c    = lane & 15;       // feature chunk
    const float4* z4 = reinterpret_cast<const float4*>(g_z);
    float4 acc = make_float4(0.f, 0.f, 0.f, 0.f);
    for (int base = beg; base < end; base += 32) {
        int cnt = min(32, end - base);
        int idx = 0; float w = 0.f;
        if (lane < cnt) { idx = __ldg(g_csr_src + base + lane); w = __ldg(g_dout + idx); }
        int npair = (cnt + 1) >> 1;
        #pragma unroll 4
        for (int j = 0; j < npair; ++j) {
            int slot = 2 * j + half;
            int s    = __shfl_sync(0xffffffffu, idx, slot & 31);
            float ww = __shfl_sync(0xffffffffu, w, slot & 31);
            if (slot < cnt) {
                float4 v = __ldg(z4 + (size_t)s * 16 + c);
                acc.x = fmaf(ww, v.x, acc.x);
                acc.y = fmaf(ww, v.y, acc.y);
                acc.z = fmaf(ww, v.z, acc.z);
                acc.w = fmaf(ww, v.w, acc.w);
            }
        }
    }
    // combine the two edge-halves
    acc.x += __shfl_xor_sync(0xffffffffu, acc.x, 16);
    acc.y += __shfl_xor_sync(0xffffffffu, acc.y, 16);
    acc.z += __shfl_xor_sync(0xffffffffu, acc.z, 16);
    acc.w += __shfl_xor_sync(0xffffffffu, acc.w, 16);
    if (half == 0) {
        float di = g_din[node];
        acc.x *= di; acc.y *= di; acc.z *= di; acc.w *= di;
        size_t o = (size_t)node * 64 + c * 4;
        split_store4(acc, g_agg3h + o, g_agg3l + o);
    }
}

// ============================================================================
// Persistent tensor-core GEMMs: W staged once per CTA, prefetch next x tile
// (pre-split bf16 planes -> staging is raw uint2 copies). Split-bf16 3-term MMA.
// ============================================================================

#define LOAD_A(frag, plane, rowb, kk, S)                                          \
    {                                                                             \
        int _o = (rowb) * (S) + (kk);                                             \
        frag[0] = *(const unsigned*)((plane) + _o);                               \
        frag[1] = *(const unsigned*)((plane) + _o + 8 * (S));                     \
        frag[2] = *(const unsigned*)((plane) + _o + 8);                           \
        frag[3] = *(const unsigned*)((plane) + _o + 8 * (S) + 8);                 \
    }

// ---------------- GEMM1: h1 = relu(agg1[128] @ W1 -> 256 cols), split output ----
__global__ void gemm1_mma(const float* __restrict__ bias, int N, int ntiles) {
    const int S = 136;
    extern __shared__ __nv_bfloat16 sm[];
    __nv_bfloat16* xh = sm;
    __nv_bfloat16* xl = xh + 64 * S;
    __nv_bfloat16* wh = xl + 64 * S;
    __nv_bfloat16* wl = wh + 256 * S;
    int tid = threadIdx.x;

    {
        const unsigned* sh = (const unsigned*)g_w1t_hi;
        const unsigned* sl = (const unsigned*)g_w1t_lo;
        unsigned* dh = (unsigned*)wh;
        unsigned* dl = (unsigned*)wl;
        for (int j = tid; j < 256 * 64; j += 256) {
            int r = j >> 6, c2 = j & 63;
            dh[r * 68 + c2] = sh[j];
            dl[r * 68 + c2] = sl[j];
        }
    }

    int wid = tid >> 5, lane = tid & 31;
    int g = lane >> 2, t2 = (lane & 3) * 2;
    int wr = wid & 1, wc = wid >> 1;

    uint2 pfh[8], pfl[8];
    const uint2 z2 = make_uint2(0u, 0u);
    int tile = blockIdx.x;
    if (tile < ntiles) {
        int row0 = tile * 64;
        #pragma unroll
        for (int j = 0; j < 8; ++j) {
            int i = tid + j * 256;
            int r = i >> 5, c4 = i & 31;
            int n = row0 + r;
            pfh[j] = (n < N) ? __ldg((const uint2*)g_agg1h + (size_t)n * 32 + c4) : z2;
            pfl[j] = (n < N) ? __ldg((const uint2*)g_agg1l + (size_t)n * 32 + c4) : z2;
        }
    }

    for (; tile < ntiles; tile += gridDim.x) {
        int row0 = tile * 64;
        #pragma unroll
        for (int j = 0; j < 8; ++j) {
            int i = tid + j * 256;
            int r = i >> 5, c4 = i & 31;
            *reinterpret_cast<uint2*>(xh + r * S + c4 * 4) = pfh[j];
            *reinterpret_cast<uint2*>(xl + r * S + c4 * 4) = pfl[j];
        }
        __syncthreads();

        int tnext = tile + gridDim.x;
        if (tnext < ntiles) {
            int rn0 = tnext * 64;
            #pragma unroll
            for (int j = 0; j < 8; ++j) {
                int i = tid + j * 256;
                int r = i >> 5, c4 = i & 31;
                int n = rn0 + r;
                pfh[j] = (n < N) ? __ldg((const uint2*)g_agg1h + (size_t)n * 32 + c4) : z2;
                pfl[j] = (n < N) ? __ldg((const uint2*)g_agg1l + (size_t)n * 32 + c4) : z2;
            }
        }

        float acc[2][8][4];
        #pragma unroll
        for (int a = 0; a < 2; ++a)
            #pragma unroll
            for (int b = 0; b < 8; ++b)
                #pragma unroll
                for (int c = 0; c < 4; ++c) acc[a][b][c] = 0.f;

        #pragma unroll
        for (int k0 = 0; k0 < 128; k0 += 16) {
            unsigned ah[2][4], al[2][4];
            #pragma unroll
            for (int mt = 0; mt < 2; ++mt) {
                int rb = wr * 32 + mt * 16 + g;
                LOAD_A(ah[mt], xh, rb, k0 + t2, S);
                LOAD_A(al[mt], xl, rb, k0 + t2, S);
            }
            #pragma unroll
            for (int nt = 0; nt < 8; ++nt) {
                int bo = (wc * 64 + nt * 8 + g) * S + k0 + t2;
                unsigned bh0 = *(const unsigned*)(wh + bo);
                unsigned bh1 = *(const unsigned*)(wh + bo + 8);
                unsigned bl0 = *(const unsigned*)(wl + bo);
                unsigned bl1 = *(const unsigned*)(wl + bo + 8);
                #pragma unroll
                for (int mt = 0; mt < 2; ++mt) {
                    mma_bf16(acc[mt][nt], ah[mt], bh0, bh1);
                    mma_bf16(acc[mt][nt], ah[mt], bl0, bl1);
                    mma_bf16(acc[mt][nt], al[mt], bh0, bh1);
                }
            }
        }

        #pragma unroll
        for (int nt = 0; nt < 8; ++nt) {
            int col = wc * 64 + nt * 8 + t2;
            float b0 = __ldg(bias + col), b1v = __ldg(bias + col + 1);
            #pragma unroll
            for (int mt = 0; mt < 2; ++mt) {
                #pragma unroll
                for (int hh = 0; hh < 2; ++hh) {
                    int r = row0 + wr * 32 + mt * 16 + g + hh * 8;
                    if (r < N) {
                        float v0 = fmaxf(acc[mt][nt][hh * 2]     + b0,  0.f);
                        float v1 = fmaxf(acc[mt][nt][hh * 2 + 1] + b1v, 0.f);
                        __nv_bfloat16 h0, l0, h1b, l1b;
                        split2(v0, h0, l0);
                        split2(v1, h1b, l1b);
                        __nv_bfloat162 hv; hv.x = h0; hv.y = h1b;
                        __nv_bfloat162 lv; lv.x = l0; lv.y = l1b;
                        *reinterpret_cast<__nv_bfloat162*>(g_h1h + (size_t)r * 256 + col) = hv;
                        *reinterpret_cast<__nv_bfloat162*>(g_h1l + (size_t)r * 256 + col) = lv;
                    }
                }
            }
        }
        __syncthreads();
    }
}

// ---------------- GEMM2: y2 = dout * (h1[256] @ W2 -> 128 cols), fp32 output ----
__global__ void gemm2_mma(int N, int ntiles) {
    const int S = 264;
    extern __shared__ __nv_bfloat16 sm[];
    __nv_bfloat16* xh = sm;
    __nv_bfloat16* xl = xh + 64 * S;
    __nv_bfloat16* wh = xl + 64 * S;
    __nv_bfloat16* wl = wh + 128 * S;
    int tid = threadIdx.x;

    {
        const unsigned* sh = (const unsigned*)g_w2t_hi;
        const unsigned* sl = (const unsigned*)g_w2t_lo;
        unsigned* dh = (unsigned*)wh;
        unsigned* dl = (unsigned*)wl;
        for (int j = tid; j < 128 * 128; j += 256) {
            int r = j >> 7, c2 = j & 127;
            dh[r * 132 + c2] = sh[j];
            dl[r * 132 + c2] = sl[j];
        }
    }

    int wid = tid >> 5, lane = tid & 31;
    int g = lane >> 2, t2 = (lane & 3) * 2;
    int wr = wid & 1, wc = wid >> 1;

    uint2 pfh[16], pfl[16];
    const uint2 z2 = make_uint2(0u, 0u);
    int tile = blockIdx.x;
    if (tile < ntiles) {
        int row0 = tile * 64;
        #pragma unroll
        for (int j = 0; j < 16; ++j) {
            int i = tid + j * 256;
            int r = i >> 6, c4 = i & 63;
            int n = row0 + r;
            pfh[j] = (n < N) ? __ldg((const uint2*)g_h1h + (size_t)n * 64 + c4) : z2;
            pfl[j] = (n < N) ? __ldg((const uint2*)g_h1l + (size_t)n * 64 + c4) : z2;
        }
    }

    for (; tile < ntiles; tile += gridDim.x) {
        int row0 = tile * 64;
        #pragma unroll
        for (int j = 0; j < 16; ++j) {
            int i = tid + j * 256;
            int r = i >> 6, c4 = i & 63;
            *reinterpret_cast<uint2*>(xh + r * S + c4 * 4) = pfh[j];
            *reinterpret_cast<uint2*>(xl + r * S + c4 * 4) = pfl[j];
        }
        __syncthreads();

        int tnext = tile + gridDim.x;
        if (tnext < ntiles) {
            int rn0 = tnext * 64;
            #pragma unroll
            for (int j = 0; j < 16; ++j) {
                int i = tid + j * 256;
                int r = i >> 6, c4 = i & 63;
                int n = rn0 + r;
                pfh[j] = (n < N) ? __ldg((const uint2*)g_h1h + (size_t)n * 64 + c4) : z2;
                pfl[j] = (n < N) ? __ldg((const uint2*)g_h1l + (size_t)n * 64 + c4) : z2;
            }
        }

        float acc[2][4][4];
        #pragma unroll
        for (int a = 0; a < 2; ++a)
            #pragma unroll
            for (int b = 0; b < 4; ++b)
                #pragma unroll
                for (int c = 0; c < 4; ++c) acc[a][b][c] = 0.f;

        #pragma unroll
        for (int k0 = 0; k0 < 256; k0 += 16) {
            unsigned ah[2][4], al[2][4];
            #pragma unroll
            for (int mt = 0; mt < 2; ++mt) {
                int rb = wr * 32 + mt * 16 + g;
                LOAD_A(ah[mt], xh, rb, k0 + t2, S);
                LOAD_A(al[mt], xl, rb, k0 + t2, S);
            }
            #pragma unroll
            for (int nt = 0; nt < 4; ++nt) {
                int bo = (wc * 32 + nt * 8 + g) * S + k0 + t2;
                unsigned bh0 = *(const unsigned*)(wh + bo);
                unsigned bh1 = *(const unsigned*)(wh + bo + 8);
                unsigned bl0 = *(const unsigned*)(wl + bo);
                unsigned bl1 = *(const unsigned*)(wl + bo + 8);
                #pragma unroll
                for (int mt = 0; mt < 2; ++mt) {
                    mma_bf16(acc[mt][nt], ah[mt], bh0, bh1);
                    mma_bf16(acc[mt][nt], ah[mt], bl0, bl1);
                    mma_bf16(acc[mt][nt], al[mt], bh0, bh1);
                }
            }
        }

        #pragma unroll
        for (int nt = 0; nt < 4; ++nt) {
            int col = wc * 32 + nt * 8 + t2;
            #pragma unroll
            for (int mt = 0; mt < 2; ++mt) {
                #pragma unroll
                for (int hh = 0; hh < 2; ++hh) {
                    int r = row0 + wr * 32 + mt * 16 + g + hh * 8;
                    if (r < N) {
                        float s = __ldg(g_dout + r);
                        g_y2[(size_t)r * 128 + col]     = acc[mt][nt][hh * 2]     * s;
                        g_y2[(size_t)r * 128 + col + 1] = acc[mt][nt][hh * 2 + 1] * s;
                    }
                }
            }
        }
        __syncthreads();
    }
}

// ---------------- GEMM3: recon = agg3[64] @ W3 -> 128 cols + b3 ----------------
__global__ void gemm3_mma(const float* __restrict__ bias, float* __restrict__ out,
                          int N, int ntiles) {
    const int S = 72;
    extern __shared__ __nv_bfloat16 sm[];
    __nv_bfloat16* xh = sm;
    __nv_bfloat16* xl = xh + 64 * S;
    __nv_bfloat16* wh = xl + 64 * S;
    __nv_bfloat16* wl = wh + 128 * S;
    int tid = threadIdx.x;

    {
        const unsigned* sh = (const unsigned*)g_w3t_hi;
        const unsigned* sl = (const unsigned*)g_w3t_lo;
        unsigned* dh = (unsigned*)wh;
        unsigned* dl = (unsigned*)wl;
        for (int j = tid; j < 128 * 32; j += 256) {
            int r = j >> 5, c2 = j & 31;
            dh[r * 36 + c2] = sh[j];
            dl[r * 36 + c2] = sl[j];
        }
    }

    int wid = tid >> 5, lane = tid & 31;
    int g = lane >> 2, t2 = (lane & 3) * 2;
    int wr = wid & 1, wc = wid >> 1;

    uint2 pfh[4], pfl[4];
    const uint2 z2 = make_uint2(0u, 0u);
    int tile = blockIdx.x;
    if (tile < ntiles) {
        int row0 = tile * 64;
        #pragma unroll
        for (int j = 0; j < 4; ++j) {
            int i = tid + j * 256;
            int r = i >> 4, c4 = i & 15;
            int n = row0 + r;
            pfh[j] = (n < N) ? __ldg((const uint2*)g_agg3h + (size_t)n * 16 + c4) : z2;
            pfl[j] = (n < N) ? __ldg((const uint2*)g_agg3l + (size_t)n * 16 + c4) : z2;
        }
    }

    for (; tile < ntiles; tile += gridDim.x) {
        int row0 = tile * 64;
        #pragma unroll
        for (int j = 0; j < 4; ++j) {
            int i = tid + j * 256;
            int r = i >> 4, c4 = i & 15;
            *reinterpret_cast<uint2*>(xh + r * S + c4 * 4) = pfh[j];
            *reinterpret_cast<uint2*>(xl + r * S + c4 * 4) = pfl[j];
        }
        __syncthreads();

        int tnext = tile + gridDim.x;
        if (tnext < ntiles) {
            int rn0 = tnext * 64;
            #pragma unroll
            for (int j = 0; j < 4; ++j) {
                int i = tid + j * 256;
                int r = i >> 4, c4 = i & 15;
                int n = rn0 + r;
                pfh[j] = (n < N) ? __ldg((const uint2*)g_agg3h + (size_t)n * 16 + c4) : z2;
                pfl[j] = (n < N) ? __ldg((const uint2*)g_agg3l + (size_t)n * 16 + c4) : z2;
            }
        }

        float acc[2][4][4];
        #pragma unroll
        for (int a = 0; a < 2; ++a)
            #pragma unroll
            for (int b = 0; b < 4; ++b)
                #pragma unroll
                for (int c = 0; c < 4; ++c) acc[a][b][c] = 0.f;

        #pragma unroll
        for (int k0 = 0; k0 < 64; k0 += 16) {
            unsigned ah[2][4], al[2][4];
            #pragma unroll
            for (int mt = 0; mt < 2; ++mt) {
                int rb = wr * 32 + mt * 16 + g;
                LOAD_A(ah[mt], xh, rb, k0 + t2, S);
                LOAD_A(al[mt], xl, rb, k0 + t2, S);
            }
            #pragma unroll
            for (int nt = 0; nt < 4; ++nt) {
                int bo = (wc * 32 + nt * 8 + g) * S + k0 + t2;
                unsigned bh0 = *(const unsigned*)(wh + bo);
                unsigned bh1 = *(const unsigned*)(wh + bo + 8);
                unsigned bl0 = *(const unsigned*)(wl + bo);
                unsigned bl1 = *(const unsigned*)(wl + bo + 8);
                #pragma unroll
                for (int mt = 0; mt < 2; ++mt) {
                    mma_bf16(acc[mt][nt], ah[mt], bh0, bh1);
                    mma_bf16(acc[mt][nt], ah[mt], bl0, bl1);
                    mma_bf16(acc[mt][nt], al[mt], bh0, bh1);
                }
            }
        }

        #pragma unroll
        for (int nt = 0; nt < 4; ++nt) {
            int col = wc * 32 + nt * 8 + t2;
            float b0 = __ldg(bias + col), b1v = __ldg(bias + col + 1);
            #pragma unroll
            for (int mt = 0; mt < 2; ++mt) {
                #pragma unroll
                for (int hh = 0; hh < 2; ++hh) {
                    int r = row0 + wr * 32 + mt * 16 + g + hh * 8;
                    if (r < N) {
                        out[(size_t)r * 128 + col]     = acc[mt][nt][hh * 2]     + b0;
                        out[(size_t)r * 128 + col + 1] = acc[mt][nt][hh * 2 + 1] + b1v;
                    }
                }
            }
        }
        __syncthreads();
    }
}

// ---------------- launch ----------------
extern "C" void kernel_launch(void* const* d_in, const int* in_sizes, int n_in,
                              void* d_out, int out_size) {
    const float* features = (const float*)d_in[0];
    const int*   src      = (const int*)  d_in[1];
    const int*   dst      = (const int*)  d_in[2];
    const float* eps      = (const float*)d_in[3];
    const float* W1       = (const float*)d_in[4];
    const float* b1       = (const float*)d_in[5];
    const float* W2       = (const float*)d_in[6];
    const float* b2       = (const float*)d_in[7];
    const float* W3       = (const float*)d_in[8];
    const float* b3       = (const float*)d_in[9];

    int N = in_sizes[0] / 128;
    int E = in_sizes[1];

    float* out   = (float*)d_out;
    float* recon = out;
    float* mean  = out + (size_t)N * 128;
    float* logv  = mean + (size_t)N * 64;

    const int SMEM_G1 = (64 * 136 * 2 + 256 * 136 * 2) * 2;   // ~170KB
    const int SMEM_G2 = (64 * 264 * 2 + 128 * 264 * 2) * 2;   // ~198KB
    const int SMEM_G3 = (64 * 72 * 2 + 128 * 72 * 2) * 2;     // ~54KB
    cudaFuncSetAttribute(gemm1_mma, cudaFuncAttributeMaxDynamicSharedMemorySize, SMEM_G1);
    cudaFuncSetAttribute(gemm2_mma, cudaFuncAttributeMaxDynamicSharedMemorySize, SMEM_G2);
    cudaFuncSetAttribute(gemm3_mma, cudaFuncAttributeMaxDynamicSharedMemorySize, SMEM_G3);

    int ntiles = (N + 63) / 64;
    int nb = (N + SCAN_B - 1) / SCAN_B;
    const int GRID_P = 152;
    const int GRID_P3 = 152 * 4;

    int prep_n = (N > 256 * 128) ? N : 256 * 128;
    prep_kernel<<<(prep_n + 255) / 256, 256>>>(W1, W2, W3, N);
    hist_kernel<<<(E / 4 + 255) / 256, 256>>>(src, dst, E);
    scan_part<<<nb, SCAN_B>>>(N);
    scan_tops<<<1, 32>>>(nb);
    scan_add<<<(N + 255) / 256, 256>>>(N, E);
    fill_kernel<<<(E / 4 + 255) / 256, 256>>>(src, dst, E);

    gather_d128_l1<<<(N * 32 + 255) / 256, 256>>>(features, N);
    gemm1_mma<<<GRID_P, 256, SMEM_G1>>>(b1, N, ntiles);

    gemm2_mma<<<GRID_P, 256, SMEM_G2>>>(N, ntiles);
    gather_d128_l2_vae<<<(N * 32 + 255) / 256, 256>>>(b2, eps, mean, logv, N);

    gather_d64_l3<<<(N * 32 + 255) / 256, 256>>>(N);
    gemm3_mma<<<GRID_P3, 256, SMEM_G3>>>(b3, recon, N, ntiles);
}

// round 8
// speedup vs baseline: 1.0769x; 1.0769x over previous
#include <cuda_runtime.h>
#include <cuda_bf16.h>
#include <math.h>

#define MAXN 100000
#define MAXE 1600000
#define SCAN_B 1024

// ---------------- scratch (static device globals only) ----------------
__device__ int   g_cnt_in [MAXN];
__device__ int   g_cnt_out[MAXN];
__device__ int   g_fill   [MAXN];
__device__ int   g_rowptr [MAXN + 1];
__device__ int   g_csr_src[MAXE];
__device__ int   g_blocksums[1024];
__device__ float g_dout[MAXN];
__device__ float g_din [MAXN];
__device__ float g_y2  [(size_t)MAXN * 128];
__device__ float g_z   [(size_t)MAXN * 64];

// split-bf16 activation planes (producer-side split; same bytes as fp32)
__device__ __align__(16) __nv_bfloat16 g_agg1h[(size_t)MAXN * 128];
__device__ __align__(16) __nv_bfloat16 g_agg1l[(size_t)MAXN * 128];
__device__ __align__(16) __nv_bfloat16 g_h1h  [(size_t)MAXN * 256];
__device__ __align__(16) __nv_bfloat16 g_h1l  [(size_t)MAXN * 256];
__device__ __align__(16) __nv_bfloat16 g_agg3h[(size_t)MAXN * 64];
__device__ __align__(16) __nv_bfloat16 g_agg3l[(size_t)MAXN * 64];

// split-bf16 transposed weights: W^T stored [n][k], hi + lo planes
__device__ __align__(16) __nv_bfloat16 g_w1t_hi[256 * 128], g_w1t_lo[256 * 128];
__device__ __align__(16) __nv_bfloat16 g_w2t_hi[128 * 256], g_w2t_lo[128 * 256];
__device__ __align__(16) __nv_bfloat16 g_w3t_hi[128 * 64],  g_w3t_lo[128 * 64];

// ---------------- helpers ----------------
__device__ __forceinline__ void mma_bf16(float* c, const unsigned* a, unsigned b0, unsigned b1) {
    asm volatile(
        "mma.sync.aligned.m16n8k16.row.col.f32.bf16.bf16.f32 "
        "{%0,%1,%2,%3}, {%4,%5,%6,%7}, {%8,%9}, {%0,%1,%2,%3};\n"
        : "+f"(c[0]), "+f"(c[1]), "+f"(c[2]), "+f"(c[3])
        : "r"(a[0]), "r"(a[1]), "r"(a[2]), "r"(a[3]), "r"(b0), "r"(b1));
}

__device__ __forceinline__ void split2(float v, __nv_bfloat16& h, __nv_bfloat16& l) {
    h = __float2bfloat16(v);
    l = __float2bfloat16(v - __bfloat162float(h));
}

// split a float4 and store as uint2 pairs into bf16 planes
__device__ __forceinline__ void split_store4(float4 v, __nv_bfloat16* ph, __nv_bfloat16* pl) {
    __nv_bfloat16 h[4], l[4];
    split2(v.x, h[0], l[0]); split2(v.y, h[1], l[1]);
    split2(v.z, h[2], l[2]); split2(v.w, h[3], l[3]);
    *reinterpret_cast<uint2*>(ph) = *reinterpret_cast<uint2*>(h);
    *reinterpret_cast<uint2*>(pl) = *reinterpret_cast<uint2*>(l);
}

// ---------------- weight preprocessing + counter zero (merged) ----------------
__global__ void prep_kernel(const float* __restrict__ W1, const float* __restrict__ W2,
                            const float* __restrict__ W3, int N) {
    int i = blockIdx.x * blockDim.x + threadIdx.x;
    if (i < N) { g_cnt_in[i] = 0; g_cnt_out[i] = 0; g_fill[i] = 0; }
    if (i < 128 * 256) {                 // W1 [k=128][n=256] -> T[n][k]
        int k = i >> 8, n = i & 255;
        split2(W1[i], g_w1t_hi[n * 128 + k], g_w1t_lo[n * 128 + k]);
    }
    if (i < 256 * 128) {                 // W2 [k=256][n=128] -> T[n][k]
        int k = i >> 7, n = i & 127;
        split2(W2[i], g_w2t_hi[n * 256 + k], g_w2t_lo[n * 256 + k]);
    }
    if (i < 64 * 128) {                  // W3 [k=64][n=128] -> T[n][k]
        int k = i >> 7, n = i & 127;
        split2(W3[i], g_w3t_hi[n * 64 + k], g_w3t_lo[n * 64 + k]);
    }
}

// ---------------- CSR build ----------------
__global__ void hist_kernel(const int* __restrict__ src, const int* __restrict__ dst, int E) {
    int i = (blockIdx.x * blockDim.x + threadIdx.x) * 4;
    if (i + 3 < E) {
        int4 s = *reinterpret_cast<const int4*>(src + i);
        int4 d = *reinterpret_cast<const int4*>(dst + i);
        atomicAdd(&g_cnt_out[s.x], 1); atomicAdd(&g_cnt_out[s.y], 1);
        atomicAdd(&g_cnt_out[s.z], 1); atomicAdd(&g_cnt_out[s.w], 1);
        atomicAdd(&g_cnt_in [d.x], 1); atomicAdd(&g_cnt_in [d.y], 1);
        atomicAdd(&g_cnt_in [d.z], 1); atomicAdd(&g_cnt_in [d.w], 1);
    } else {
        for (; i < E; ++i) {
            atomicAdd(&g_cnt_out[src[i]], 1);
            atomicAdd(&g_cnt_in [dst[i]], 1);
        }
    }
}

__global__ void scan_part(int N) {
    __shared__ int sm[SCAN_B];
    int tid = threadIdx.x;
    int i = blockIdx.x * SCAN_B + tid;
    int v = (i < N) ? g_cnt_in[i] : 0;
    sm[tid] = v;
    __syncthreads();
    #pragma unroll
    for (int off = 1; off < SCAN_B; off <<= 1) {
        int t = (tid >= off) ? sm[tid - off] : 0;
        __syncthreads();
        sm[tid] += t;
        __syncthreads();
    }
    if (i < N) g_rowptr[i] = sm[tid] - v;
    if (tid == SCAN_B - 1) g_blocksums[blockIdx.x] = sm[tid];
}

// parallel exclusive scan over <=128 block sums (one 128-thread block)
__global__ void scan_tops(int nb) {
    __shared__ int sm[128];
    int tid = threadIdx.x;
    int v = (tid < nb) ? g_blocksums[tid] : 0;
    sm[tid] = v;
    __syncthreads();
    #pragma unroll
    for (int off = 1; off < 128; off <<= 1) {
        int t = (tid >= off) ? sm[tid - off] : 0;
        __syncthreads();
        sm[tid] += t;
        __syncthreads();
    }
    if (tid < nb) g_blocksums[tid] = sm[tid] - v;   // exclusive
}

// scan finalize + rsqrt degrees (merged)
__global__ void scan_add(int N, int E) {
    int i = blockIdx.x * blockDim.x + threadIdx.x;
    if (i < N) {
        g_rowptr[i] += g_blocksums[i / SCAN_B];
        g_dout[i] = rsqrtf((float)max(g_cnt_out[i], 1));
        g_din [i] = rsqrtf((float)max(g_cnt_in [i], 1));
    }
    if (i == 0) g_rowptr[N] = E;
}

__global__ void fill_kernel(const int* __restrict__ src, const int* __restrict__ dst, int E) {
    int i = (blockIdx.x * blockDim.x + threadIdx.x) * 4;
    if (i + 3 < E) {
        int4 s = *reinterpret_cast<const int4*>(src + i);
        int4 d = *reinterpret_cast<const int4*>(dst + i);
        int p;
        p = g_rowptr[d.x] + atomicAdd(&g_fill[d.x], 1); g_csr_src[p] = s.x;
        p = g_rowptr[d.y] + atomicAdd(&g_fill[d.y], 1); g_csr_src[p] = s.y;
        p = g_rowptr[d.z] + atomicAdd(&g_fill[d.z], 1); g_csr_src[p] = s.z;
        p = g_rowptr[d.w] + atomicAdd(&g_fill[d.w], 1); g_csr_src[p] = s.w;
    } else {
        for (; i < E; ++i) {
            int d = dst[i];
            int pos = g_rowptr[d] + atomicAdd(&g_fill[d], 1);
            g_csr_src[pos] = src[i];
        }
    }
}

// ---------------- gathers (atomic-free CSR, broadcast-LDG indices) ----------------
// layer1: agg1 = din * segsum(dout * x), D=128, warp/node, split-bf16 output
__global__ void gather_d128_l1(const float* __restrict__ x, int N) {
    int t = blockIdx.x * blockDim.x + threadIdx.x;
    int node = t >> 5, lane = t & 31;
    if (node >= N) return;
    int beg = g_rowptr[node], end = g_rowptr[node + 1];
    const float4* x4 = reinterpret_cast<const float4*>(x);
    float4 acc = make_float4(0.f, 0.f, 0.f, 0.f);
    #pragma unroll 4
    for (int k = beg; k < end; ++k) {
        int s = __ldg(g_csr_src + k);
        float w = __ldg(g_dout + s);
        float4 v = __ldg(x4 + (size_t)s * 32 + lane);
        acc.x = fmaf(w, v.x, acc.x);
        acc.y = fmaf(w, v.y, acc.y);
        acc.z = fmaf(w, v.z, acc.z);
        acc.w = fmaf(w, v.w, acc.w);
    }
    float di = g_din[node];
    acc.x *= di; acc.y *= di; acc.z *= di; acc.w *= di;
    size_t o = (size_t)node * 128 + lane * 4;
    split_store4(acc, g_agg1h + o, g_agg1l + o);
}

// layer2 fused VAE epilogue: ml = din * segsum(y2) + b2; split; z = eps*exp(.5lv)+mean
__global__ void gather_d128_l2_vae(const float* __restrict__ b2, const float* __restrict__ eps,
                                   float* __restrict__ out_mean, float* __restrict__ out_lv, int N) {
    int t = blockIdx.x * blockDim.x + threadIdx.x;
    int node = t >> 5, lane = t & 31;
    if (node >= N) return;
    int beg = g_rowptr[node], end = g_rowptr[node + 1];
    const float4* y4 = reinterpret_cast<const float4*>(g_y2);
    float4 acc = make_float4(0.f, 0.f, 0.f, 0.f);
    #pragma unroll 4
    for (int k = beg; k < end; ++k) {
        int s = __ldg(g_csr_src + k);
        float4 v = __ldg(y4 + (size_t)s * 32 + lane);
        acc.x += v.x; acc.y += v.y; acc.z += v.z; acc.w += v.w;
    }
    float di = g_din[node];
    float4 bb = __ldg(reinterpret_cast<const float4*>(b2) + lane);
    acc.x = fmaf(acc.x, di, bb.x);
    acc.y = fmaf(acc.y, di, bb.y);
    acc.z = fmaf(acc.z, di, bb.z);
    acc.w = fmaf(acc.w, di, bb.w);
    float4 other;
    other.x = __shfl_xor_sync(0xffffffffu, acc.x, 16);
    other.y = __shfl_xor_sync(0xffffffffu, acc.y, 16);
    other.z = __shfl_xor_sync(0xffffffffu, acc.z, 16);
    other.w = __shfl_xor_sync(0xffffffffu, acc.w, 16);
    if (lane < 16) {
        size_t o = (size_t)node * 16 + lane;
        reinterpret_cast<float4*>(out_mean)[o] = acc;
        float4 e = __ldg(reinterpret_cast<const float4*>(eps) + o);
        float4 z;
        z.x = fmaf(e.x, expf(0.5f * other.x), acc.x);
        z.y = fmaf(e.y, expf(0.5f * other.y), acc.y);
        z.z = fmaf(e.z, expf(0.5f * other.z), acc.z);
        z.w = fmaf(e.w, expf(0.5f * other.w), acc.w);
        reinterpret_cast<float4*>(g_z)[o] = z;
    } else {
        reinterpret_cast<float4*>(out_lv)[(size_t)node * 16 + (lane - 16)] = acc;
    }
}

// layer3: agg3 = din * segsum(dout * z), D=64, 16 threads/node, split-bf16 output
__global__ void gather_d64_l3(int N) {
    int t = blockIdx.x * blockDim.x + threadIdx.x;
    int node = t >> 4, lane = t & 15;
    if (node >= N) return;
    int beg = g_rowptr[node], end = g_rowptr[node + 1];
    const float4* z4 = reinterpret_cast<const float4*>(g_z);
    float4 acc = make_float4(0.f, 0.f, 0.f, 0.f);
    #pragma unroll 4
    for (int k = beg; k < end; ++k) {
        int s = __ldg(g_csr_src + k);
        float w = __ldg(g_dout + s);
        float4 v = __ldg(z4 + (size_t)s * 16 + lane);
        acc.x = fmaf(w, v.x, acc.x);
        acc.y = fmaf(w, v.y, acc.y);
        acc.z = fmaf(w, v.z, acc.z);
        acc.w = fmaf(w, v.w, acc.w);
    }
    float di = g_din[node];
    acc.x *= di; acc.y *= di; acc.z *= di; acc.w *= di;
    size_t o = (size_t)node * 64 + lane * 4;
    split_store4(acc, g_agg3h + o, g_agg3l + o);
}

// ============================================================================
// Persistent tensor-core GEMMs: W staged once per CTA, prefetch next x tile
// (pre-split bf16 planes -> staging is raw uint2 copies). Split-bf16 3-term MMA.
// ============================================================================

#define LOAD_A(frag, plane, rowb, kk, S)                                          \
    {                                                                             \
        int _o = (rowb) * (S) + (kk);                                             \
        frag[0] = *(const unsigned*)((plane) + _o);                               \
        frag[1] = *(const unsigned*)((plane) + _o + 8 * (S));                     \
        frag[2] = *(const unsigned*)((plane) + _o + 8);                           \
        frag[3] = *(const unsigned*)((plane) + _o + 8 * (S) + 8);                 \
    }

// ---------------- GEMM1: h1 = relu(agg1[128] @ W1 -> 256 cols), split output ----
__global__ void gemm1_mma(const float* __restrict__ bias, int N, int ntiles) {
    const int S = 136;
    extern __shared__ __nv_bfloat16 sm[];
    __nv_bfloat16* xh = sm;
    __nv_bfloat16* xl = xh + 64 * S;
    __nv_bfloat16* wh = xl + 64 * S;
    __nv_bfloat16* wl = wh + 256 * S;
    int tid = threadIdx.x;

    {
        const unsigned* sh = (const unsigned*)g_w1t_hi;
        const unsigned* sl = (const unsigned*)g_w1t_lo;
        unsigned* dh = (unsigned*)wh;
        unsigned* dl = (unsigned*)wl;
        for (int j = tid; j < 256 * 64; j += 256) {
            int r = j >> 6, c2 = j & 63;
            dh[r * 68 + c2] = sh[j];
            dl[r * 68 + c2] = sl[j];
        }
    }

    int wid = tid >> 5, lane = tid & 31;
    int g = lane >> 2, t2 = (lane & 3) * 2;
    int wr = wid & 1, wc = wid >> 1;

    uint2 pfh[8], pfl[8];
    const uint2 z2 = make_uint2(0u, 0u);
    int tile = blockIdx.x;
    if (tile < ntiles) {
        int row0 = tile * 64;
        #pragma unroll
        for (int j = 0; j < 8; ++j) {
            int i = tid + j * 256;
            int r = i >> 5, c4 = i & 31;
            int n = row0 + r;
            pfh[j] = (n < N) ? __ldg((const uint2*)g_agg1h + (size_t)n * 32 + c4) : z2;
            pfl[j] = (n < N) ? __ldg((const uint2*)g_agg1l + (size_t)n * 32 + c4) : z2;
        }
    }

    for (; tile < ntiles; tile += gridDim.x) {
        int row0 = tile * 64;
        #pragma unroll
        for (int j = 0; j < 8; ++j) {
            int i = tid + j * 256;
            int r = i >> 5, c4 = i & 31;
            *reinterpret_cast<uint2*>(xh + r * S + c4 * 4) = pfh[j];
            *reinterpret_cast<uint2*>(xl + r * S + c4 * 4) = pfl[j];
        }
        __syncthreads();

        int tnext = tile + gridDim.x;
        if (tnext < ntiles) {
            int rn0 = tnext * 64;
            #pragma unroll
            for (int j = 0; j < 8; ++j) {
                int i = tid + j * 256;
                int r = i >> 5, c4 = i & 31;
                int n = rn0 + r;
                pfh[j] = (n < N) ? __ldg((const uint2*)g_agg1h + (size_t)n * 32 + c4) : z2;
                pfl[j] = (n < N) ? __ldg((const uint2*)g_agg1l + (size_t)n * 32 + c4) : z2;
            }
        }

        float acc[2][8][4];
        #pragma unroll
        for (int a = 0; a < 2; ++a)
            #pragma unroll
            for (int b = 0; b < 8; ++b)
                #pragma unroll
                for (int c = 0; c < 4; ++c) acc[a][b][c] = 0.f;

        #pragma unroll
        for (int k0 = 0; k0 < 128; k0 += 16) {
            unsigned ah[2][4], al[2][4];
            #pragma unroll
            for (int mt = 0; mt < 2; ++mt) {
                int rb = wr * 32 + mt * 16 + g;
                LOAD_A(ah[mt], xh, rb, k0 + t2, S);
                LOAD_A(al[mt], xl, rb, k0 + t2, S);
            }
            #pragma unroll
            for (int nt = 0; nt < 8; ++nt) {
                int bo = (wc * 64 + nt * 8 + g) * S + k0 + t2;
                unsigned bh0 = *(const unsigned*)(wh + bo);
                unsigned bh1 = *(const unsigned*)(wh + bo + 8);
                unsigned bl0 = *(const unsigned*)(wl + bo);
                unsigned bl1 = *(const unsigned*)(wl + bo + 8);
                #pragma unroll
                for (int mt = 0; mt < 2; ++mt) {
                    mma_bf16(acc[mt][nt], ah[mt], bh0, bh1);
                    mma_bf16(acc[mt][nt], ah[mt], bl0, bl1);
                    mma_bf16(acc[mt][nt], al[mt], bh0, bh1);
                }
            }
        }

        #pragma unroll
        for (int nt = 0; nt < 8; ++nt) {
            int col = wc * 64 + nt * 8 + t2;
            float b0 = __ldg(bias + col), b1v = __ldg(bias + col + 1);
            #pragma unroll
            for (int mt = 0; mt < 2; ++mt) {
                #pragma unroll
                for (int hh = 0; hh < 2; ++hh) {
                    int r = row0 + wr * 32 + mt * 16 + g + hh * 8;
                    if (r < N) {
                        float v0 = fmaxf(acc[mt][nt][hh * 2]     + b0,  0.f);
                        float v1 = fmaxf(acc[mt][nt][hh * 2 + 1] + b1v, 0.f);
                        __nv_bfloat16 h0, l0, h1b, l1b;
                        split2(v0, h0, l0);
                        split2(v1, h1b, l1b);
                        __nv_bfloat162 hv; hv.x = h0; hv.y = h1b;
                        __nv_bfloat162 lv; lv.x = l0; lv.y = l1b;
                        *reinterpret_cast<__nv_bfloat162*>(g_h1h + (size_t)r * 256 + col) = hv;
                        *reinterpret_cast<__nv_bfloat162*>(g_h1l + (size_t)r * 256 + col) = lv;
                    }
                }
            }
        }
        __syncthreads();
    }
}

// ---------------- GEMM2: y2 = dout * (h1[256] @ W2 -> 128 cols), fp32 output ----
__global__ void gemm2_mma(int N, int ntiles) {
    const int S = 264;
    extern __shared__ __nv_bfloat16 sm[];
    __nv_bfloat16* xh = sm;
    __nv_bfloat16* xl = xh + 64 * S;
    __nv_bfloat16* wh = xl + 64 * S;
    __nv_bfloat16* wl = wh + 128 * S;
    int tid = threadIdx.x;

    {
        const unsigned* sh = (const unsigned*)g_w2t_hi;
        const unsigned* sl = (const unsigned*)g_w2t_lo;
        unsigned* dh = (unsigned*)wh;
        unsigned* dl = (unsigned*)wl;
        for (int j = tid; j < 128 * 128; j += 256) {
            int r = j >> 7, c2 = j & 127;
            dh[r * 132 + c2] = sh[j];
            dl[r * 132 + c2] = sl[j];
        }
    }

    int wid = tid >> 5, lane = tid & 31;
    int g = lane >> 2, t2 = (lane & 3) * 2;
    int wr = wid & 1, wc = wid >> 1;

    uint2 pfh[16], pfl[16];
    const uint2 z2 = make_uint2(0u, 0u);
    int tile = blockIdx.x;
    if (tile < ntiles) {
        int row0 = tile * 64;
        #pragma unroll
        for (int j = 0; j < 16; ++j) {
            int i = tid + j * 256;
            int r = i >> 6, c4 = i & 63;
            int n = row0 + r;
            pfh[j] = (n < N) ? __ldg((const uint2*)g_h1h + (size_t)n * 64 + c4) : z2;
            pfl[j] = (n < N) ? __ldg((const uint2*)g_h1l + (size_t)n * 64 + c4) : z2;
        }
    }

    for (; tile < ntiles; tile += gridDim.x) {
        int row0 = tile * 64;
        #pragma unroll
        for (int j = 0; j < 16; ++j) {
            int i = tid + j * 256;
            int r = i >> 6, c4 = i & 63;
            *reinterpret_cast<uint2*>(xh + r * S + c4 * 4) = pfh[j];
            *reinterpret_cast<uint2*>(xl + r * S + c4 * 4) = pfl[j];
        }
        __syncthreads();

        int tnext = tile + gridDim.x;
        if (tnext < ntiles) {
            int rn0 = tnext * 64;
            #pragma unroll
            for (int j = 0; j < 16; ++j) {
                int i = tid + j * 256;
                int r = i >> 6, c4 = i & 63;
                int n = rn0 + r;
                pfh[j] = (n < N) ? __ldg((const uint2*)g_h1h + (size_t)n * 64 + c4) : z2;
                pfl[j] = (n < N) ? __ldg((const uint2*)g_h1l + (size_t)n * 64 + c4) : z2;
            }
        }

        float acc[2][4][4];
        #pragma unroll
        for (int a = 0; a < 2; ++a)
            #pragma unroll
            for (int b = 0; b < 4; ++b)
                #pragma unroll
                for (int c = 0; c < 4; ++c) acc[a][b][c] = 0.f;

        #pragma unroll
        for (int k0 = 0; k0 < 256; k0 += 16) {
            unsigned ah[2][4], al[2][4];
            #pragma unroll
            for (int mt = 0; mt < 2; ++mt) {
                int rb = wr * 32 + mt * 16 + g;
                LOAD_A(ah[mt], xh, rb, k0 + t2, S);
                LOAD_A(al[mt], xl, rb, k0 + t2, S);
            }
            #pragma unroll
            for (int nt = 0; nt < 4; ++nt) {
                int bo = (wc * 32 + nt * 8 + g) * S + k0 + t2;
                unsigned bh0 = *(const unsigned*)(wh + bo);
                unsigned bh1 = *(const unsigned*)(wh + bo + 8);
                unsigned bl0 = *(const unsigned*)(wl + bo);
                unsigned bl1 = *(const unsigned*)(wl + bo + 8);
                #pragma unroll
                for (int mt = 0; mt < 2; ++mt) {
                    mma_bf16(acc[mt][nt], ah[mt], bh0, bh1);
                    mma_bf16(acc[mt][nt], ah[mt], bl0, bl1);
                    mma_bf16(acc[mt][nt], al[mt], bh0, bh1);
                }
            }
        }

        #pragma unroll
        for (int nt = 0; nt < 4; ++nt) {
            int col = wc * 32 + nt * 8 + t2;
            #pragma unroll
            for (int mt = 0; mt < 2; ++mt) {
                #pragma unroll
                for (int hh = 0; hh < 2; ++hh) {
                    int r = row0 + wr * 32 + mt * 16 + g + hh * 8;
                    if (r < N) {
                        float s = __ldg(g_dout + r);
                        g_y2[(size_t)r * 128 + col]     = acc[mt][nt][hh * 2]     * s;
                        g_y2[(size_t)r * 128 + col + 1] = acc[mt][nt][hh * 2 + 1] * s;
                    }
                }
            }
        }
        __syncthreads();
    }
}

// ---------------- GEMM3: recon = agg3[64] @ W3 -> 128 cols + b3 ----------------
__global__ void gemm3_mma(const float* __restrict__ bias, float* __restrict__ out,
                          int N, int ntiles) {
    const int S = 72;
    extern __shared__ __nv_bfloat16 sm[];
    __nv_bfloat16* xh = sm;
    __nv_bfloat16* xl = xh + 64 * S;
    __nv_bfloat16* wh = xl + 64 * S;
    __nv_bfloat16* wl = wh + 128 * S;
    int tid = threadIdx.x;

    {
        const unsigned* sh = (const unsigned*)g_w3t_hi;
        const unsigned* sl = (const unsigned*)g_w3t_lo;
        unsigned* dh = (unsigned*)wh;
        unsigned* dl = (unsigned*)wl;
        for (int j = tid; j < 128 * 32; j += 256) {
            int r = j >> 5, c2 = j & 31;
            dh[r * 36 + c2] = sh[j];
            dl[r * 36 + c2] = sl[j];
        }
    }

    int wid = tid >> 5, lane = tid & 31;
    int g = lane >> 2, t2 = (lane & 3) * 2;
    int wr = wid & 1, wc = wid >> 1;

    uint2 pfh[4], pfl[4];
    const uint2 z2 = make_uint2(0u, 0u);
    int tile = blockIdx.x;
    if (tile < ntiles) {
        int row0 = tile * 64;
        #pragma unroll
        for (int j = 0; j < 4; ++j) {
            int i = tid + j * 256;
            int r = i >> 4, c4 = i & 15;
            int n = row0 + r;
            pfh[j] = (n < N) ? __ldg((const uint2*)g_agg3h + (size_t)n * 16 + c4) : z2;
            pfl[j] = (n < N) ? __ldg((const uint2*)g_agg3l + (size_t)n * 16 + c4) : z2;
        }
    }

    for (; tile < ntiles; tile += gridDim.x) {
        int row0 = tile * 64;
        #pragma unroll
        for (int j = 0; j < 4; ++j) {
            int i = tid + j * 256;
            int r = i >> 4, c4 = i & 15;
            *reinterpret_cast<uint2*>(xh + r * S + c4 * 4) = pfh[j];
            *reinterpret_cast<uint2*>(xl + r * S + c4 * 4) = pfl[j];
        }
        __syncthreads();

        int tnext = tile + gridDim.x;
        if (tnext < ntiles) {
            int rn0 = tnext * 64;
            #pragma unroll
            for (int j = 0; j < 4; ++j) {
                int i = tid + j * 256;
                int r = i >> 4, c4 = i & 15;
                int n = rn0 + r;
                pfh[j] = (n < N) ? __ldg((const uint2*)g_agg3h + (size_t)n * 16 + c4) : z2;
                pfl[j] = (n < N) ? __ldg((const uint2*)g_agg3l + (size_t)n * 16 + c4) : z2;
            }
        }

        float acc[2][4][4];
        #pragma unroll
        for (int a = 0; a < 2; ++a)
            #pragma unroll
            for (int b = 0; b < 4; ++b)
                #pragma unroll
                for (int c = 0; c < 4; ++c) acc[a][b][c] = 0.f;

        #pragma unroll
        for (int k0 = 0; k0 < 64; k0 += 16) {
            unsigned ah[2][4], al[2][4];
            #pragma unroll
            for (int mt = 0; mt < 2; ++mt) {
                int rb = wr * 32 + mt * 16 + g;
                LOAD_A(ah[mt], xh, rb, k0 + t2, S);
                LOAD_A(al[mt], xl, rb, k0 + t2, S);
            }
            #pragma unroll
            for (int nt = 0; nt < 4; ++nt) {
                int bo = (wc * 32 + nt * 8 + g) * S + k0 + t2;
                unsigned bh0 = *(const unsigned*)(wh + bo);
                unsigned bh1 = *(const unsigned*)(wh + bo + 8);
                unsigned bl0 = *(const unsigned*)(wl + bo);
                unsigned bl1 = *(const unsigned*)(wl + bo + 8);
                #pragma unroll
                for (int mt = 0; mt < 2; ++mt) {
                    mma_bf16(acc[mt][nt], ah[mt], bh0, bh1);
                    mma_bf16(acc[mt][nt], ah[mt], bl0, bl1);
                    mma_bf16(acc[mt][nt], al[mt], bh0, bh1);
                }
            }
        }

        #pragma unroll
        for (int nt = 0; nt < 4; ++nt) {
            int col = wc * 32 + nt * 8 + t2;
            float b0 = __ldg(bias + col), b1v = __ldg(bias + col + 1);
            #pragma unroll
            for (int mt = 0; mt < 2; ++mt) {
                #pragma unroll
                for (int hh = 0; hh < 2; ++hh) {
                    int r = row0 + wr * 32 + mt * 16 + g + hh * 8;
                    if (r < N) {
                        out[(size_t)r * 128 + col]     = acc[mt][nt][hh * 2]     + b0;
                        out[(size_t)r * 128 + col + 1] = acc[mt][nt][hh * 2 + 1] + b1v;
                    }
                }
            }
        }
        __syncthreads();
    }
}

// ---------------- launch ----------------
extern "C" void kernel_launch(void* const* d_in, const int* in_sizes, int n_in,
                              void* d_out, int out_size) {
    const float* features = (const float*)d_in[0];
    const int*   src      = (const int*)  d_in[1];
    const int*   dst      = (const int*)  d_in[2];
    const float* eps      = (const float*)d_in[3];
    const float* W1       = (const float*)d_in[4];
    const float* b1       = (const float*)d_in[5];
    const float* W2       = (const float*)d_in[6];
    const float* b2       = (const float*)d_in[7];
    const float* W3       = (const float*)d_in[8];
    const float* b3       = (const float*)d_in[9];

    int N = in_sizes[0] / 128;
    int E = in_sizes[1];

    float* out   = (float*)d_out;
    float* recon = out;
    float* mean  = out + (size_t)N * 128;
    float* logv  = mean + (size_t)N * 64;

    const int SMEM_G1 = (64 * 136 * 2 + 256 * 136 * 2) * 2;   // ~170KB
    const int SMEM_G2 = (64 * 264 * 2 + 128 * 264 * 2) * 2;   // ~198KB
    const int SMEM_G3 = (64 * 72 * 2 + 128 * 72 * 2) * 2;     // ~54KB
    cudaFuncSetAttribute(gemm1_mma, cudaFuncAttributeMaxDynamicSharedMemorySize, SMEM_G1);
    cudaFuncSetAttribute(gemm2_mma, cudaFuncAttributeMaxDynamicSharedMemorySize, SMEM_G2);
    cudaFuncSetAttribute(gemm3_mma, cudaFuncAttributeMaxDynamicSharedMemorySize, SMEM_G3);

    int ntiles = (N + 63) / 64;
    int nb = (N + SCAN_B - 1) / SCAN_B;
    const int GRID_P = 152;
    const int GRID_P3 = 152 * 4;

    int prep_n = (N > 256 * 128) ? N : 256 * 128;
    prep_kernel<<<(prep_n + 255) / 256, 256>>>(W1, W2, W3, N);
    hist_kernel<<<(E / 4 + 255) / 256, 256>>>(src, dst, E);
    scan_part<<<nb, SCAN_B>>>(N);
    scan_tops<<<1, 128>>>(nb);
    scan_add<<<(N + 255) / 256, 256>>>(N, E);
    fill_kernel<<<(E / 4 + 255) / 256, 256>>>(src, dst, E);

    gather_d128_l1<<<(N * 32 + 255) / 256, 256>>>(features, N);
    gemm1_mma<<<GRID_P, 256, SMEM_G1>>>(b1, N, ntiles);

    gemm2_mma<<<GRID_P, 256, SMEM_G2>>>(N, ntiles);
    gather_d128_l2_vae<<<(N * 32 + 255) / 256, 256>>>(b2, eps, mean, logv, N);

    gather_d64_l3<<<(N * 16 + 255) / 256, 256>>>(N);
    gemm3_mma<<<GRID_P3, 256, SMEM_G3>>>(b3, recon, N, ntiles);
}